// round 15
// baseline (speedup 1.0000x reference)
#include <cuda_runtime.h>
#include <cstdint>

#define D        64
#define K        1024
#define NVEC     65536
#define QELEMS   (NVEC * D)
#define MTILE    128
#define NCHUNK   64
#define NCHUNKS  (K / NCHUNK)     // 16
#define GRID     (NVEC / MTILE)   // 512
#define BLOCK    128              // 4 warps; each warp M=32 rows
#define EPS16    1200             // ~0.018 in 2^-16 units; int8-quant guard

// smem: A tile (16KB, prologue-only) aliases the B double-buffer (2 x 8KB)
#define OFF_B    0            // 2 stages x 8192 ([Hi|Lo] s8 rows, swizzled)
#define OFF_SN   16384        // 1024 int32 en16
#define OFF_IDX  20480        // 128 ints
#define OFF_FLG  20992        // 128 ints
#define OFF_RED  21504        // 4 floats
#define SMEM_SZ  21632

__device__ int8_t g_B[K * 128];              // per codeword: [Hi(64) | Lo(64)] s8
__device__ float  g_enorm2[K];               // exact fp32 |e|^2 (rescan)
__device__ int    g_en16[K];                 // round(|e|^2 * 65536)
__device__ int    g_flag_list[NVEC];
__device__ int    g_flag_count;

// ---------- helpers ----------
__device__ __forceinline__ uint32_t smem_u32(const void* p) {
    uint32_t a;
    asm("{ .reg .u64 t; cvta.to.shared.u64 t, %1; cvt.u32.u64 %0, t; }" : "=r"(a) : "l"(p));
    return a;
}
__device__ __forceinline__ void cp16(uint32_t dst, const void* src) {
    asm volatile("cp.async.cg.shared.global [%0], [%1], 16;" :: "r"(dst), "l"(src));
}
__device__ __forceinline__ void cp_commit() { asm volatile("cp.async.commit_group;" ::: "memory"); }
template<int N> __device__ __forceinline__ void cp_wait() {
    asm volatile("cp.async.wait_group %0;" :: "n"(N) : "memory");
}
__device__ __forceinline__ void ldsm4(uint32_t* r, uint32_t addr) {
    asm volatile("ldmatrix.sync.aligned.m8n8.x4.shared.b16 {%0,%1,%2,%3}, [%4];"
                 : "=r"(r[0]), "=r"(r[1]), "=r"(r[2]), "=r"(r[3]) : "r"(addr));
}
// int8 MMA: m16n8k32, exact s32 accumulate
__device__ __forceinline__ void mma_s8(int* c, const uint32_t* a, uint32_t b0, uint32_t b1) {
    asm volatile(
        "mma.sync.aligned.m16n8k32.row.col.s32.s8.s8.s32 "
        "{%0,%1,%2,%3}, {%4,%5,%6,%7}, {%8,%9}, {%0,%1,%2,%3};"
        : "+r"(c[0]), "+r"(c[1]), "+r"(c[2]), "+r"(c[3])
        : "r"(a[0]), "r"(a[1]), "r"(a[2]), "r"(a[3]), "r"(b0), "r"(b1));
}
__device__ __forceinline__ void sts16(uint32_t addr, uint4 v) {
    asm volatile("st.shared.v4.b32 [%0], {%1, %2, %3, %4};"
                 :: "r"(addr), "r"(v.x), "r"(v.y), "r"(v.z), "r"(v.w));
}
__device__ __forceinline__ void quant8(float f, int& hx, int& lx) {
    int X = __float2int_rn(f * 4096.f);
    hx = (X + 128) >> 8;                     // round-to-nearest high digit
    lx = X - (hx << 8);                      // in [-128, 127]
}
__device__ __forceinline__ uint32_t pack4(int b0, int b1, int b2, int b3) {
    return (uint32_t)(b0 & 255) | ((uint32_t)(b1 & 255) << 8) |
           ((uint32_t)(b2 & 255) << 16) | ((uint32_t)(b3 & 255) << 24);
}

// ---------- codebook conversion: s8 Hi|Lo + norms ----------
__global__ void __launch_bounds__(256) vq_convE(const float* __restrict__ emb) {
    int t = blockIdx.x * 256 + threadIdx.x;     // 0 .. 8K-1
    if (t == 0) g_flag_count = 0;
    int k = t >> 3, j = t & 7;
    const float4* er = reinterpret_cast<const float4*>(emb + (size_t)k * D + j * 8);
    float4 a = er[0], b = er[1];
    float f[8] = {a.x, a.y, a.z, a.w, b.x, b.y, b.z, b.w};
    int h[8], lo[8];
    float s = 0.f;
#pragma unroll
    for (int e = 0; e < 8; e++) {
        s += f[e] * f[e];
        quant8(f[e], h[e], lo[e]);
    }
    uint32_t* rowh = reinterpret_cast<uint32_t*>(g_B + (size_t)k * 128 + j * 8);
    uint32_t* rowl = reinterpret_cast<uint32_t*>(g_B + (size_t)k * 128 + 64 + j * 8);
    rowh[0] = pack4(h[0], h[1], h[2], h[3]);   rowh[1] = pack4(h[4], h[5], h[6], h[7]);
    rowl[0] = pack4(lo[0], lo[1], lo[2], lo[3]); rowl[1] = pack4(lo[4], lo[5], lo[6], lo[7]);
#pragma unroll
    for (int off = 4; off > 0; off >>= 1) s += __shfl_xor_sync(0xffffffffu, s, off);
    if (j == 0) { g_enorm2[k] = s; g_en16[k] = __float2int_rn(s * 65536.f); }
}

// load one B chunk (64 rows x 128B = 8KB)
__device__ __forceinline__ void load_B(uint32_t sb, int chunk, int stage, int tid) {
    uint32_t base = sb + OFF_B + stage * 8192;
    const char* s1 = reinterpret_cast<const char*>(g_B + (size_t)chunk * NCHUNK * 128);
#pragma unroll
    for (int it = 0; it < 4; it++) {
        int i = tid + it * BLOCK;               // 0..511 (64 rows x 8 segs)
        int row = i >> 3, seg = i & 7;
        cp16(base + row * 128 + ((seg ^ (row & 7)) << 4), s1 + row * 128 + seg * 16);
    }
}

#define UPDI(dv, nn, B1v, I1v, B2v) \
    if ((dv) < (B1v)) { (B2v) = (B1v); (B1v) = (dv); (I1v) = (nn); } \
    else if ((dv) < (B2v)) { (B2v) = (dv); }

#define MERGEI(B1v, I1v, B2v, off) { \
    int p1 = __shfl_xor_sync(0xffffffffu, B1v, off); \
    int pi = __shfl_xor_sync(0xffffffffu, I1v, off); \
    int p2 = __shfl_xor_sync(0xffffffffu, B2v, off); \
    if (p1 < (B1v) || (p1 == (B1v) && pi < (I1v))) { (B2v) = min((B1v), p2); (B1v) = p1; (I1v) = pi; } \
    else                                            { (B2v) = min((B2v), p1); } }

// ---------- mega kernel: A-quant + int8 GEMM + exact-int argmin + finalize ----------
__global__ void __launch_bounds__(BLOCK, 2) vq_gemm(const float* __restrict__ x,
                                                    const float* __restrict__ emb,
                                                    float* __restrict__ out, int out_size) {
    extern __shared__ char sm[];
    uint32_t sb = smem_u32(sm);
    const int tid = threadIdx.x, wid = tid >> 5, l = tid & 31;

    // en16 via cp.async
#pragma unroll
    for (int it = 0; it < 2; it++)
        cp16(sb + OFF_SN + (tid + it * BLOCK) * 16,
             reinterpret_cast<const char*>(g_en16) + (tid + it * BLOCK) * 16);
    cp_commit();                                // G: SN

    // A tile -> aliased B region: LDG fp32, quantize Hi/Lo s8, STS swizzled
    {
        const int row = tid;
        const float4* xr = reinterpret_cast<const float4*>(
            x + (size_t)(blockIdx.x * MTILE + row) * D);
        uint32_t abase = sb + OFF_B + row * 128;
#pragma unroll
        for (int i = 0; i < 4; i++) {           // 16 floats -> 16B Hi + 16B Lo
            float4 q0 = xr[4*i], q1 = xr[4*i+1], q2 = xr[4*i+2], q3 = xr[4*i+3];
            float f[16] = {q0.x,q0.y,q0.z,q0.w, q1.x,q1.y,q1.z,q1.w,
                           q2.x,q2.y,q2.z,q2.w, q3.x,q3.y,q3.z,q3.w};
            int h[16], lo[16];
#pragma unroll
            for (int e = 0; e < 16; e++) quant8(f[e], h[e], lo[e]);
            uint4 HV = {pack4(h[0],h[1],h[2],h[3]),   pack4(h[4],h[5],h[6],h[7]),
                        pack4(h[8],h[9],h[10],h[11]), pack4(h[12],h[13],h[14],h[15])};
            uint4 LV = {pack4(lo[0],lo[1],lo[2],lo[3]),   pack4(lo[4],lo[5],lo[6],lo[7]),
                        pack4(lo[8],lo[9],lo[10],lo[11]), pack4(lo[12],lo[13],lo[14],lo[15])};
            sts16(abase + ((i ^ (row & 7)) << 4),       HV);   // Hi: segs 0..3
            sts16(abase + (((4 + i) ^ (row & 7)) << 4), LV);   // Lo: segs 4..7
        }
    }
    __syncthreads();                            // A visible

    // hoist A fragments: part p (0=Hi,1=Lo), a-block, kstep(2 x k32)
    uint32_t aF[2][2][2][4];
#pragma unroll
    for (int p = 0; p < 2; p++)
#pragma unroll
        for (int a = 0; a < 2; a++) {
            int row = (wid << 5) + (a << 4) + (l & 15);
            uint32_t rb = sb + OFF_B + row * 128;
#pragma unroll
            for (int ks = 0; ks < 2; ks++) {
                int seg = p * 4 + ks * 2 + (l >> 4);
                ldsm4(aF[p][a][ks], rb + ((seg ^ (row & 7)) << 4));
            }
        }
    __syncthreads();                            // A reads done; B may overwrite

    load_B(sb, 0, 0, tid);
    cp_commit();                                // G: B0
    load_B(sb, 1, 1, tid);
    cp_commit();                                // G: B1
    cp_wait<1>();                               // SN + B0 resident
    __syncthreads();

    const int* snp = reinterpret_cast<const int*>(sm + OFF_SN);

    int b1a = 0x7FFFFFFF, b2a = 0x7FFFFFFF, b1b = 0x7FFFFFFF, b2b = 0x7FFFFFFF;
    int b1c = 0x7FFFFFFF, b2c = 0x7FFFFFFF, b1d = 0x7FFFFFFF, b2d = 0x7FFFFFFF;
    int i1a = 0, i1b = 0, i1c = 0, i1d = 0;

    for (int c = 0; c < NCHUNKS; c++) {
        if (c > 0) { cp_wait<1>(); __syncthreads(); }
        uint32_t stage = sb + OFF_B + (c & 1) * 8192;

#pragma unroll
        for (int half = 0; half < 2; half++) {
            int HH[2][4][4], CR[2][4][4], LL[2][4][4];
#pragma unroll
            for (int a = 0; a < 2; a++)
#pragma unroll
                for (int t = 0; t < 4; t++) {
                    HH[a][t][0]=HH[a][t][1]=HH[a][t][2]=HH[a][t][3]=0;
                    CR[a][t][0]=CR[a][t][1]=CR[a][t][2]=CR[a][t][3]=0;
                    LL[a][t][0]=LL[a][t][1]=LL[a][t][2]=LL[a][t][3]=0;
                }

            // B-Hi segs: A-Hi -> HH, A-Lo -> CR
#pragma unroll
            for (int ks = 0; ks < 2; ks++)
#pragma unroll
                for (int g = 0; g < 2; g++) {
                    int row = (half << 5) + (g << 4) + (l & 15);
                    int seg = ks * 2 + (l >> 4);
                    uint32_t r[4];
                    ldsm4(r, stage + row * 128 + ((seg ^ (row & 7)) << 4));
                    mma_s8(HH[0][2*g],   aF[0][0][ks], r[0], r[2]);
                    mma_s8(HH[0][2*g+1], aF[0][0][ks], r[1], r[3]);
                    mma_s8(HH[1][2*g],   aF[0][1][ks], r[0], r[2]);
                    mma_s8(HH[1][2*g+1], aF[0][1][ks], r[1], r[3]);
                    mma_s8(CR[0][2*g],   aF[1][0][ks], r[0], r[2]);
                    mma_s8(CR[0][2*g+1], aF[1][0][ks], r[1], r[3]);
                    mma_s8(CR[1][2*g],   aF[1][1][ks], r[0], r[2]);
                    mma_s8(CR[1][2*g+1], aF[1][1][ks], r[1], r[3]);
                }
            // B-Lo segs: A-Hi -> CR, A-Lo -> LL
#pragma unroll
            for (int ks = 0; ks < 2; ks++)
#pragma unroll
                for (int g = 0; g < 2; g++) {
                    int row = (half << 5) + (g << 4) + (l & 15);
                    int seg = 4 + ks * 2 + (l >> 4);
                    uint32_t r[4];
                    ldsm4(r, stage + row * 128 + ((seg ^ (row & 7)) << 4));
                    mma_s8(CR[0][2*g],   aF[0][0][ks], r[0], r[2]);
                    mma_s8(CR[0][2*g+1], aF[0][0][ks], r[1], r[3]);
                    mma_s8(CR[1][2*g],   aF[0][1][ks], r[0], r[2]);
                    mma_s8(CR[1][2*g+1], aF[0][1][ks], r[1], r[3]);
                    mma_s8(LL[0][2*g],   aF[1][0][ks], r[0], r[2]);
                    mma_s8(LL[0][2*g+1], aF[1][0][ks], r[1], r[3]);
                    mma_s8(LL[1][2*g],   aF[1][1][ks], r[0], r[2]);
                    mma_s8(LL[1][2*g+1], aF[1][1][ks], r[1], r[3]);
                }

            // epilogue (exact int32): d16 = en16 - 2*(HH*256 + CR + LL>>8)
#pragma unroll
            for (int t = 0; t < 4; t++) {
                int n0 = c * NCHUNK + (half << 5) + t * 8 + 2 * (l & 3);
                int s0 = snp[n0], s1 = snp[n0 + 1];
                int d;
                d = s0 - 2 * (HH[0][t][0] * 256 + CR[0][t][0] + (LL[0][t][0] >> 8));
                UPDI(d, n0,     b1a, i1a, b2a);
                d = s1 - 2 * (HH[0][t][1] * 256 + CR[0][t][1] + (LL[0][t][1] >> 8));
                UPDI(d, n0 + 1, b1a, i1a, b2a);
                d = s0 - 2 * (HH[0][t][2] * 256 + CR[0][t][2] + (LL[0][t][2] >> 8));
                UPDI(d, n0,     b1b, i1b, b2b);
                d = s1 - 2 * (HH[0][t][3] * 256 + CR[0][t][3] + (LL[0][t][3] >> 8));
                UPDI(d, n0 + 1, b1b, i1b, b2b);
                d = s0 - 2 * (HH[1][t][0] * 256 + CR[1][t][0] + (LL[1][t][0] >> 8));
                UPDI(d, n0,     b1c, i1c, b2c);
                d = s1 - 2 * (HH[1][t][1] * 256 + CR[1][t][1] + (LL[1][t][1] >> 8));
                UPDI(d, n0 + 1, b1c, i1c, b2c);
                d = s0 - 2 * (HH[1][t][2] * 256 + CR[1][t][2] + (LL[1][t][2] >> 8));
                UPDI(d, n0,     b1d, i1d, b2d);
                d = s1 - 2 * (HH[1][t][3] * 256 + CR[1][t][3] + (LL[1][t][3] >> 8));
                UPDI(d, n0 + 1, b1d, i1d, b2d);
            }
        }

        __syncthreads();
        if (c + 2 < NCHUNKS) load_B(sb, c + 2, c & 1, tid);
        cp_commit();
    }

    // cross-lane merge within 4-lane groups
#pragma unroll
    for (int off = 1; off <= 2; off <<= 1) {
        MERGEI(b1a, i1a, b2a, off);
        MERGEI(b1b, i1b, b2b, off);
        MERGEI(b1c, i1c, b2c, off);
        MERGEI(b1d, i1d, b2d, off);
    }

    int* sidx = reinterpret_cast<int*>(sm + OFF_IDX);
    int* sflg = reinterpret_cast<int*>(sm + OFF_FLG);
    if ((l & 3) == 0) {
        int r0 = (wid << 5) + (l >> 2);         // rows r0, +8, +16, +24
        int v = blockIdx.x * MTILE + r0;
        int fa = (b2a - b1a <= EPS16), fb = (b2b - b1b <= EPS16);
        int fc = (b2c - b1c <= EPS16), fd = (b2d - b1d <= EPS16);
        sidx[r0]      = i1a; sflg[r0]      = fa;
        sidx[r0 + 8]  = i1b; sflg[r0 + 8]  = fb;
        sidx[r0 + 16] = i1c; sflg[r0 + 16] = fc;
        sidx[r0 + 24] = i1d; sflg[r0 + 24] = fd;
        if (fa) { int s = atomicAdd(&g_flag_count, 1); g_flag_list[s] = v; }
        if (fb) { int s = atomicAdd(&g_flag_count, 1); g_flag_list[s] = v + 8; }
        if (fc) { int s = atomicAdd(&g_flag_count, 1); g_flag_list[s] = v + 16; }
        if (fd) { int s = atomicAdd(&g_flag_count, 1); g_flag_list[s] = v + 24; }
    }
    __syncthreads();

    // fused finalize for non-flagged vectors (1 thread/vector, exact fp32)
    {
        const int r = tid;
        const int v = blockIdx.x * MTILE + r;
        float lsum = 0.f;
        if (!sflg[r]) {
            int bi = sidx[r];
            const float4* er = reinterpret_cast<const float4*>(emb + (size_t)bi * D);
            const float4* xr = reinterpret_cast<const float4*>(x + (size_t)v * D);
            float4* o = reinterpret_cast<float4*>(out + (size_t)v * D);
#pragma unroll
            for (int i = 0; i < 16; i++) {
                float4 e = er[i]; float4 xx = xr[i];
                float dx = e.x - xx.x, dy = e.y - xx.y, dz = e.z - xx.z, dw = e.w - xx.w;
                lsum += dx * dx + dy * dy + dz * dz + dw * dw;
                float4 q;   // quantized = x + (e - x)
                q.x = xx.x + dx; q.y = xx.y + dy; q.z = xx.z + dz; q.w = xx.w + dw;
                o[i] = q;
            }
            if (QELEMS + 1 + v < out_size) out[QELEMS + 1 + v] = (float)bi;
        }
#pragma unroll
        for (int off = 16; off > 0; off >>= 1)
            lsum += __shfl_down_sync(0xffffffffu, lsum, off);
        float* sred = reinterpret_cast<float*>(sm + OFF_RED);
        if (l == 0) sred[wid] = lsum;
        __syncthreads();
        if (wid == 0) {
            float s = (l < 4) ? sred[l] : 0.f;
#pragma unroll
            for (int off = 2; off > 0; off >>= 1)
                s += __shfl_down_sync(0xffffffffu, s, off);
            if (l == 0 && out_size > QELEMS)
                atomicAdd(out + QELEMS, s * (0.25f / (float)QELEMS));
        }
    }
}

// ---------- exact rescan + full finalize for flagged vectors ----------
__global__ void __launch_bounds__(256) vq_rescan(const float* __restrict__ x,
                                                 const float* __restrict__ emb,
                                                 float* __restrict__ out, int out_size) {
    __shared__ float sx[64];
    __shared__ float sbest[256];
    __shared__ int   sidx[256];
    int n = g_flag_count;
    if (n > NVEC) n = NVEC;
    for (int vi = blockIdx.x; vi < n; vi += gridDim.x) {
        int v = g_flag_list[vi];
        __syncthreads();
        if (threadIdx.x < 16)
            reinterpret_cast<float4*>(sx)[threadIdx.x] =
                reinterpret_cast<const float4*>(x + (size_t)v * D)[threadIdx.x];
        __syncthreads();
        float best = 3.4e38f; int bi = K;
#pragma unroll
        for (int kk = 0; kk < 4; kk++) {
            int k = kk * 256 + threadIdx.x;
            const float4* er = reinterpret_cast<const float4*>(emb + (size_t)k * D);
            float dot = 0.f;
#pragma unroll
            for (int i = 0; i < 16; i++) {
                float4 e = er[i];
                dot += sx[4*i] * e.x + sx[4*i+1] * e.y + sx[4*i+2] * e.z + sx[4*i+3] * e.w;
            }
            float d = fmaf(-2.f, dot, g_enorm2[k]);
            if (d < best) { best = d; bi = k; }
        }
        sbest[threadIdx.x] = best; sidx[threadIdx.x] = bi;
        __syncthreads();
        for (int s = 128; s > 0; s >>= 1) {
            if (threadIdx.x < s) {
                float ob = sbest[threadIdx.x + s]; int oi = sidx[threadIdx.x + s];
                if (ob < sbest[threadIdx.x] ||
                    (ob == sbest[threadIdx.x] && oi < sidx[threadIdx.x])) {
                    sbest[threadIdx.x] = ob; sidx[threadIdx.x] = oi;
                }
            }
            __syncthreads();
        }
        int bfin = sidx[0];
        float lsum = 0.f;
        if (threadIdx.x < 16) {
            float4 e  = reinterpret_cast<const float4*>(emb + (size_t)bfin * D)[threadIdx.x];
            float4 xx = reinterpret_cast<const float4*>(x + (size_t)v * D)[threadIdx.x];
            float dx = e.x - xx.x, dy = e.y - xx.y, dz = e.z - xx.z, dw = e.w - xx.w;
            lsum = dx * dx + dy * dy + dz * dz + dw * dw;
            float4 q;
            q.x = xx.x + dx; q.y = xx.y + dy; q.z = xx.z + dz; q.w = xx.w + dw;
            reinterpret_cast<float4*>(out + (size_t)v * D)[threadIdx.x] = q;
        }
        if (threadIdx.x < 32) {
#pragma unroll
            for (int off = 8; off > 0; off >>= 1)
                lsum += __shfl_down_sync(0xffffffffu, lsum, off);
            if (threadIdx.x == 0) {
                if (out_size > QELEMS)
                    atomicAdd(out + QELEMS, lsum * (0.25f / (float)QELEMS));
                if (QELEMS + 1 + v < out_size) out[QELEMS + 1 + v] = (float)bfin;
            }
        }
    }
}

extern "C" void kernel_launch(void* const* d_in, const int* in_sizes, int n_in,
                              void* d_out, int out_size) {
    const float* x   = (const float*)d_in[0];
    const float* emb = (const float*)d_in[1];
    if (n_in >= 2 && in_sizes[0] == K * D && in_sizes[1] == QELEMS) {
        const float* t = x; x = emb; emb = t;
    }
    float* out = (float*)d_out;

    if (out_size > QELEMS)
        cudaMemsetAsync(out + QELEMS, 0, sizeof(float), 0);

    cudaFuncSetAttribute(vq_gemm, cudaFuncAttributeMaxDynamicSharedMemorySize, SMEM_SZ);

    vq_convE<<<K * 8 / 256, 256>>>(emb);
    vq_gemm<<<GRID, BLOCK, SMEM_SZ>>>(x, emb, out, out_size);
    vq_rescan<<<256, 256>>>(x, emb, out, out_size);
}

// round 16
// speedup vs baseline: 2.9211x; 2.9211x over previous
#include <cuda_runtime.h>
#include <cuda_bf16.h>
#include <cstdint>

#define D        64
#define K        1024
#define NVEC     65536
#define QELEMS   (NVEC * D)
#define MTILE    128
#define NCHUNK   64
#define NCHUNKS  (K / NCHUNK)     // 16
#define GRID     (NVEC / MTILE)   // 512
#define BLOCK    128              // 4 warps; each warp M=32 rows
#define EPS      0.003f

// smem offsets
#define OFF_A    0            // 128 rows x 256B (swizzled) = 32768
#define OFF_B    32768        // 2 stages x 24576 (B1 16K + B2 8K)
#define OFF_SN   81920        // 1024 floats = 4096
#define OFF_IDX  86016        // 128 ints
#define OFF_FLG  86528        // 128 ints
#define OFF_RED  87040        // 4 floats
#define SMEM_SZ  87168

__device__ __nv_bfloat16 g_B1[K * 128];      // per codeword: [h | h]
__device__ __nv_bfloat16 g_B2[K * 64];       // per codeword: [m]
__device__ float g_enorm2[K];
__device__ int   g_flag_list[NVEC];
__device__ int   g_flag_count;

// ---------- helpers ----------
__device__ __forceinline__ uint32_t smem_u32(const void* p) {
    uint32_t a;
    asm("{ .reg .u64 t; cvta.to.shared.u64 t, %1; cvt.u32.u64 %0, t; }" : "=r"(a) : "l"(p));
    return a;
}
__device__ __forceinline__ void cp16(uint32_t dst, const void* src) {
    asm volatile("cp.async.cg.shared.global [%0], [%1], 16;" :: "r"(dst), "l"(src));
}
__device__ __forceinline__ void cp_commit() { asm volatile("cp.async.commit_group;" ::: "memory"); }
template<int N> __device__ __forceinline__ void cp_wait() {
    asm volatile("cp.async.wait_group %0;" :: "n"(N) : "memory");
}
__device__ __forceinline__ void ldsm4(uint32_t* r, uint32_t addr) {
    asm volatile("ldmatrix.sync.aligned.m8n8.x4.shared.b16 {%0,%1,%2,%3}, [%4];"
                 : "=r"(r[0]), "=r"(r[1]), "=r"(r[2]), "=r"(r[3]) : "r"(addr));
}
__device__ __forceinline__ void mma16816(float* c, const uint32_t* a, uint32_t b0, uint32_t b1) {
    asm volatile(
        "mma.sync.aligned.m16n8k16.row.col.f32.bf16.bf16.f32 "
        "{%0,%1,%2,%3}, {%4,%5,%6,%7}, {%8,%9}, {%0,%1,%2,%3};"
        : "+f"(c[0]), "+f"(c[1]), "+f"(c[2]), "+f"(c[3])
        : "r"(a[0]), "r"(a[1]), "r"(a[2]), "r"(a[3]), "r"(b0), "r"(b1));
}
__device__ __forceinline__ void sts16(uint32_t addr, uint4 v) {
    asm volatile("st.shared.v4.b32 [%0], {%1, %2, %3, %4};"
                 :: "r"(addr), "r"(v.x), "r"(v.y), "r"(v.z), "r"(v.w));
}

// ---------- codebook conversion ----------
__global__ void __launch_bounds__(256) vq_convE(const float* __restrict__ emb) {
    int t = blockIdx.x * 256 + threadIdx.x;
    if (t == 0) g_flag_count = 0;
    int k = t >> 3, j = t & 7;
    const float4* er = reinterpret_cast<const float4*>(emb + (size_t)k * D + j * 8);
    float4 a = er[0], b = er[1];
    float f[8] = {a.x, a.y, a.z, a.w, b.x, b.y, b.z, b.w};
    __nv_bfloat16 h[8], m[8];
    float s = 0.f;
#pragma unroll
    for (int e = 0; e < 8; e++) {
        s += f[e] * f[e];
        h[e] = __float2bfloat16_rn(f[e]);
        m[e] = __float2bfloat16_rn(f[e] - __bfloat162float(h[e]));
    }
    uint4 hv = *reinterpret_cast<uint4*>(h);
    uint4 mv = *reinterpret_cast<uint4*>(m);
    uint4* r1 = reinterpret_cast<uint4*>(g_B1 + (size_t)k * 128 + j * 8);
    r1[0] = hv; r1[8] = hv;
    *reinterpret_cast<uint4*>(g_B2 + (size_t)k * 64 + j * 8) = mv;
#pragma unroll
    for (int off = 4; off > 0; off >>= 1) s += __shfl_xor_sync(0xffffffffu, s, off);
    if (j == 0) g_enorm2[k] = s;
}

// load one B chunk with 128 threads: B1 (64x256B) + B2 (64x128B)
__device__ __forceinline__ void load_B(uint32_t sb, int chunk, int stage, int tid) {
    uint32_t base = sb + OFF_B + stage * 24576;
    const char* s1 = reinterpret_cast<const char*>(g_B1 + (size_t)chunk * NCHUNK * 128);
    const char* s2 = reinterpret_cast<const char*>(g_B2 + (size_t)chunk * NCHUNK * 64);
#pragma unroll
    for (int it = 0; it < 8; it++) {
        int i = tid + it * BLOCK;               // 0..1023
        int row = i >> 4, seg = i & 15;
        cp16(base + row * 256 + ((seg ^ (row & 7)) << 4), s1 + row * 256 + seg * 16);
    }
#pragma unroll
    for (int it = 0; it < 4; it++) {
        int i = tid + it * BLOCK;               // 0..511
        int row = i >> 3, seg = i & 7;
        cp16(base + 16384 + row * 128 + ((seg ^ (row & 7)) << 4), s2 + row * 128 + seg * 16);
    }
}

#define UPD(dv, nn, B1v, I1v, B2v) \
    if ((dv) < (B1v)) { (B2v) = (B1v); (B1v) = (dv); (I1v) = (nn); } \
    else if ((dv) < (B2v)) { (B2v) = (dv); }

#define MERGE(B1v, I1v, B2v, off) { \
    float p1 = __shfl_xor_sync(0xffffffffu, B1v, off); \
    int   pi = __shfl_xor_sync(0xffffffffu, I1v, off); \
    float p2 = __shfl_xor_sync(0xffffffffu, B2v, off); \
    if (p1 < (B1v) || (p1 == (B1v) && pi < (I1v))) { (B2v) = fminf((B1v), p2); (B1v) = p1; (I1v) = pi; } \
    else                                            { (B2v) = fminf((B2v), p1); } }

// ---------- mega kernel: A-convert + GEMM (2 A-blocks/warp) + argmin + finalize ----------
__global__ void __launch_bounds__(BLOCK, 2) vq_gemm(const float* __restrict__ x,
                                                    const float* __restrict__ emb,
                                                    float* __restrict__ out, int out_size) {
    extern __shared__ char sm[];
    uint32_t sb = smem_u32(sm);
    const int tid = threadIdx.x, wid = tid >> 5, l = tid & 31;

    // async loads: e-norms + B0 (G0), B1 (G1)
#pragma unroll
    for (int it = 0; it < 2; it++)
        cp16(sb + OFF_SN + (tid + it * BLOCK) * 16,
             reinterpret_cast<const char*>(g_enorm2) + (tid + it * BLOCK) * 16);
    load_B(sb, 0, 0, tid);
    cp_commit();                                // G0
    load_B(sb, 1, 1, tid);
    cp_commit();                                // G1

    // A tile: one row per thread, split h/m, STS swizzled
    {
        const int row = tid;
        const float4* xr = reinterpret_cast<const float4*>(
            x + (size_t)(blockIdx.x * MTILE + row) * D);
        uint32_t abase = sb + OFF_A + row * 256;
#pragma unroll
        for (int i = 0; i < 8; i++) {           // 8 x (8 floats -> 16B h + 16B m)
            float4 a = xr[2 * i], b = xr[2 * i + 1];
            float f[8] = {a.x, a.y, a.z, a.w, b.x, b.y, b.z, b.w};
            __nv_bfloat16 h[8], m[8];
#pragma unroll
            for (int e = 0; e < 8; e++) {
                h[e] = __float2bfloat16_rn(f[e]);
                m[e] = __float2bfloat16_rn(f[e] - __bfloat162float(h[e]));
            }
            sts16(abase + ((i ^ (row & 7)) << 4),       *reinterpret_cast<uint4*>(h));
            sts16(abase + (((8 + i) ^ (row & 7)) << 4), *reinterpret_cast<uint4*>(m));
        }
    }

    cp_wait<1>();
    __syncthreads();

    // hoist A fragments: 2 blocks of 16 rows per warp, 8 k-steps each
    uint32_t aF[2][8][4];
#pragma unroll
    for (int a = 0; a < 2; a++) {
        int row = (wid << 5) + (a << 4) + (l & 15);
        uint32_t rb = sb + OFF_A + row * 256;
#pragma unroll
        for (int j = 0; j < 8; j++) {
            int seg = j * 2 + (l >> 4);
            ldsm4(aF[a][j], rb + ((seg ^ (row & 7)) << 4));
        }
    }
    const float* snp = reinterpret_cast<const float*>(sm + OFF_SN);

    float b1a = 3.4e38f, b2a = 3.4e38f, b1b = 3.4e38f, b2b = 3.4e38f;
    float b1c = 3.4e38f, b2c = 3.4e38f, b1d = 3.4e38f, b2d = 3.4e38f;
    int i1a = 0, i1b = 0, i1c = 0, i1d = 0;

    for (int c = 0; c < NCHUNKS; c++) {
        if (c > 0) { cp_wait<1>(); __syncthreads(); }
        uint32_t stage = sb + OFF_B + (c & 1) * 24576;

        float C[2][8][4];
#pragma unroll
        for (int a = 0; a < 2; a++)
#pragma unroll
            for (int t = 0; t < 8; t++) { C[a][t][0]=C[a][t][1]=C[a][t][2]=C[a][t][3]=0.f; }

        // [h|m] x [h|h] (8 k-steps): 1 B-ldsm feeds 4 HMMA
#pragma unroll
        for (int j = 0; j < 8; j++) {
#pragma unroll
            for (int g = 0; g < 4; g++) {
                int row = (g << 4) + (l & 15);
                int seg = j * 2 + (l >> 4);
                uint32_t r[4];
                ldsm4(r, stage + row * 256 + ((seg ^ (row & 7)) << 4));
                mma16816(C[0][2*g],   aF[0][j], r[0], r[2]);
                mma16816(C[0][2*g+1], aF[0][j], r[1], r[3]);
                mma16816(C[1][2*g],   aF[1][j], r[0], r[2]);
                mma16816(C[1][2*g+1], aF[1][j], r[1], r[3]);
            }
        }
        // h x [m] (4 k-steps)
#pragma unroll
        for (int j = 0; j < 4; j++) {
#pragma unroll
            for (int g = 0; g < 4; g++) {
                int row = (g << 4) + (l & 15);
                int seg = j * 2 + (l >> 4);
                uint32_t r[4];
                ldsm4(r, stage + 16384 + row * 128 + ((seg ^ (row & 7)) << 4));
                mma16816(C[0][2*g],   aF[0][j], r[0], r[2]);
                mma16816(C[0][2*g+1], aF[0][j], r[1], r[3]);
                mma16816(C[1][2*g],   aF[1][j], r[0], r[2]);
                mma16816(C[1][2*g+1], aF[1][j], r[1], r[3]);
            }
        }

        // epilogue: two-min tracking for 4 row-slots
#pragma unroll
        for (int t = 0; t < 8; t++) {
            int n0 = c * NCHUNK + t * 8 + 2 * (l & 3);
            float s0 = snp[n0], s1 = snp[n0 + 1];
            float d;
            d = fmaf(-2.f, C[0][t][0], s0); UPD(d, n0,     b1a, i1a, b2a);
            d = fmaf(-2.f, C[0][t][1], s1); UPD(d, n0 + 1, b1a, i1a, b2a);
            d = fmaf(-2.f, C[0][t][2], s0); UPD(d, n0,     b1b, i1b, b2b);
            d = fmaf(-2.f, C[0][t][3], s1); UPD(d, n0 + 1, b1b, i1b, b2b);
            d = fmaf(-2.f, C[1][t][0], s0); UPD(d, n0,     b1c, i1c, b2c);
            d = fmaf(-2.f, C[1][t][1], s1); UPD(d, n0 + 1, b1c, i1c, b2c);
            d = fmaf(-2.f, C[1][t][2], s0); UPD(d, n0,     b1d, i1d, b2d);
            d = fmaf(-2.f, C[1][t][3], s1); UPD(d, n0 + 1, b1d, i1d, b2d);
        }

        __syncthreads();
        if (c + 2 < NCHUNKS) load_B(sb, c + 2, c & 1, tid);
        cp_commit();
    }

    // cross-lane merge within 4-lane groups
#pragma unroll
    for (int off = 1; off <= 2; off <<= 1) {
        MERGE(b1a, i1a, b2a, off);
        MERGE(b1b, i1b, b2b, off);
        MERGE(b1c, i1c, b2c, off);
        MERGE(b1d, i1d, b2d, off);
    }

    int* sidx = reinterpret_cast<int*>(sm + OFF_IDX);
    int* sflg = reinterpret_cast<int*>(sm + OFF_FLG);
    if ((l & 3) == 0) {
        int r0 = (wid << 5) + (l >> 2);         // rows r0, +8, +16, +24
        int v = blockIdx.x * MTILE + r0;
        int fa = (b2a - b1a <= EPS), fb = (b2b - b1b <= EPS);
        int fc = (b2c - b1c <= EPS), fd = (b2d - b1d <= EPS);
        sidx[r0]      = i1a; sflg[r0]      = fa;
        sidx[r0 + 8]  = i1b; sflg[r0 + 8]  = fb;
        sidx[r0 + 16] = i1c; sflg[r0 + 16] = fc;
        sidx[r0 + 24] = i1d; sflg[r0 + 24] = fd;
        if (fa) { int s = atomicAdd(&g_flag_count, 1); g_flag_list[s] = v; }
        if (fb) { int s = atomicAdd(&g_flag_count, 1); g_flag_list[s] = v + 8; }
        if (fc) { int s = atomicAdd(&g_flag_count, 1); g_flag_list[s] = v + 16; }
        if (fd) { int s = atomicAdd(&g_flag_count, 1); g_flag_list[s] = v + 24; }
    }
    __syncthreads();

    // fused finalize for non-flagged vectors (1 thread/vector)
    {
        const int r = tid;
        const int v = blockIdx.x * MTILE + r;
        float lsum = 0.f;
        if (!sflg[r]) {
            int bi = sidx[r];
            const float4* er = reinterpret_cast<const float4*>(emb + (size_t)bi * D);
            const float4* xr = reinterpret_cast<const float4*>(x + (size_t)v * D);
            float4* o = reinterpret_cast<float4*>(out + (size_t)v * D);
#pragma unroll
            for (int i = 0; i < 16; i++) {
                float4 e = er[i]; float4 xx = xr[i];
                float dx = e.x - xx.x, dy = e.y - xx.y, dz = e.z - xx.z, dw = e.w - xx.w;
                lsum += dx * dx + dy * dy + dz * dz + dw * dw;
                float4 q;   // quantized = x + (e - x)
                q.x = xx.x + dx; q.y = xx.y + dy; q.z = xx.z + dz; q.w = xx.w + dw;
                o[i] = q;
            }
            if (QELEMS + 1 + v < out_size) out[QELEMS + 1 + v] = (float)bi;
        }
#pragma unroll
        for (int off = 16; off > 0; off >>= 1)
            lsum += __shfl_down_sync(0xffffffffu, lsum, off);
        float* sred = reinterpret_cast<float*>(sm + OFF_RED);
        if (l == 0) sred[wid] = lsum;
        __syncthreads();
        if (wid == 0) {
            float s = (l < 4) ? sred[l] : 0.f;
#pragma unroll
            for (int off = 2; off > 0; off >>= 1)
                s += __shfl_down_sync(0xffffffffu, s, off);
            if (l == 0 && out_size > QELEMS)
                atomicAdd(out + QELEMS, s * (0.25f / (float)QELEMS));
        }
    }
}

// ---------- exact rescan + full finalize for flagged vectors ----------
__global__ void __launch_bounds__(256) vq_rescan(const float* __restrict__ x,
                                                 const float* __restrict__ emb,
                                                 float* __restrict__ out, int out_size) {
    __shared__ float sx[64];
    __shared__ float sbest[256];
    __shared__ int   sidx[256];
    int n = g_flag_count;
    if (n > NVEC) n = NVEC;
    for (int vi = blockIdx.x; vi < n; vi += gridDim.x) {
        int v = g_flag_list[vi];
        __syncthreads();
        if (threadIdx.x < 16)
            reinterpret_cast<float4*>(sx)[threadIdx.x] =
                reinterpret_cast<const float4*>(x + (size_t)v * D)[threadIdx.x];
        __syncthreads();
        float best = 3.4e38f; int bi = K;
#pragma unroll
        for (int kk = 0; kk < 4; kk++) {
            int k = kk * 256 + threadIdx.x;
            const float4* er = reinterpret_cast<const float4*>(emb + (size_t)k * D);
            float dot = 0.f;
#pragma unroll
            for (int i = 0; i < 16; i++) {
                float4 e = er[i];
                dot += sx[4*i] * e.x + sx[4*i+1] * e.y + sx[4*i+2] * e.z + sx[4*i+3] * e.w;
            }
            float d = fmaf(-2.f, dot, g_enorm2[k]);
            if (d < best) { best = d; bi = k; }
        }
        sbest[threadIdx.x] = best; sidx[threadIdx.x] = bi;
        __syncthreads();
        for (int s = 128; s > 0; s >>= 1) {
            if (threadIdx.x < s) {
                float ob = sbest[threadIdx.x + s]; int oi = sidx[threadIdx.x + s];
                if (ob < sbest[threadIdx.x] ||
                    (ob == sbest[threadIdx.x] && oi < sidx[threadIdx.x])) {
                    sbest[threadIdx.x] = ob; sidx[threadIdx.x] = oi;
                }
            }
            __syncthreads();
        }
        int bfin = sidx[0];
        float lsum = 0.f;
        if (threadIdx.x < 16) {
            float4 e  = reinterpret_cast<const float4*>(emb + (size_t)bfin * D)[threadIdx.x];
            float4 xx = reinterpret_cast<const float4*>(x + (size_t)v * D)[threadIdx.x];
            float dx = e.x - xx.x, dy = e.y - xx.y, dz = e.z - xx.z, dw = e.w - xx.w;
            lsum = dx * dx + dy * dy + dz * dz + dw * dw;
            float4 q;
            q.x = xx.x + dx; q.y = xx.y + dy; q.z = xx.z + dz; q.w = xx.w + dw;
            reinterpret_cast<float4*>(out + (size_t)v * D)[threadIdx.x] = q;
        }
        if (threadIdx.x < 32) {
#pragma unroll
            for (int off = 8; off > 0; off >>= 1)
                lsum += __shfl_down_sync(0xffffffffu, lsum, off);
            if (threadIdx.x == 0) {
                if (out_size > QELEMS)
                    atomicAdd(out + QELEMS, lsum * (0.25f / (float)QELEMS));
                if (QELEMS + 1 + v < out_size) out[QELEMS + 1 + v] = (float)bfin;
            }
        }
    }
}

extern "C" void kernel_launch(void* const* d_in, const int* in_sizes, int n_in,
                              void* d_out, int out_size) {
    const float* x   = (const float*)d_in[0];
    const float* emb = (const float*)d_in[1];
    if (n_in >= 2 && in_sizes[0] == K * D && in_sizes[1] == QELEMS) {
        const float* t = x; x = emb; emb = t;
    }
    float* out = (float*)d_out;

    if (out_size > QELEMS)
        cudaMemsetAsync(out + QELEMS, 0, sizeof(float), 0);

    cudaFuncSetAttribute(vq_gemm, cudaFuncAttributeMaxDynamicSharedMemorySize, SMEM_SZ);

    vq_convE<<<K * 8 / 256, 256>>>(emb);
    vq_gemm<<<GRID, BLOCK, SMEM_SZ>>>(x, emb, out, out_size);
    vq_rescan<<<256, 256>>>(x, emb, out, out_size);
}

// round 17
// speedup vs baseline: 2.9640x; 1.0147x over previous
#include <cuda_runtime.h>
#include <cuda_bf16.h>
#include <cstdint>

#define D        64
#define K        1024
#define NVEC     65536
#define QELEMS   (NVEC * D)
#define MTILE    128
#define NCHUNK   64
#define NCHUNKS  (K / NCHUNK)     // 16
#define GRID     (NVEC / MTILE)   // 512
#define BLOCK    128              // 4 warps; each warp M=32 rows
#define EPS      0.003f

// smem offsets
#define OFF_A    0            // 128 rows x 256B (swizzled) = 32768
#define OFF_B    32768        // 2 stages x 24576 (B1 16K + B2 8K)
#define OFF_SN   81920        // 1024 floats = 4096
#define OFF_IDX  86016        // 128 ints
#define OFF_FLG  86528        // 128 ints
#define OFF_RED  87040        // 4 floats
#define SMEM_SZ  87168

__device__ __nv_bfloat16 g_B1[K * 128];      // per codeword: [h | h]
__device__ __nv_bfloat16 g_B2[K * 64];       // per codeword: [m]
__device__ float g_enorm2[K];
__device__ int   g_flag_list[NVEC];
__device__ int   g_flag_count;

// ---------- helpers ----------
__device__ __forceinline__ uint32_t smem_u32(const void* p) {
    uint32_t a;
    asm("{ .reg .u64 t; cvta.to.shared.u64 t, %1; cvt.u32.u64 %0, t; }" : "=r"(a) : "l"(p));
    return a;
}
__device__ __forceinline__ void cp16(uint32_t dst, const void* src) {
    asm volatile("cp.async.cg.shared.global [%0], [%1], 16;" :: "r"(dst), "l"(src));
}
__device__ __forceinline__ void cp_commit() { asm volatile("cp.async.commit_group;" ::: "memory"); }
template<int N> __device__ __forceinline__ void cp_wait() {
    asm volatile("cp.async.wait_group %0;" :: "n"(N) : "memory");
}
__device__ __forceinline__ void ldsm4(uint32_t* r, uint32_t addr) {
    asm volatile("ldmatrix.sync.aligned.m8n8.x4.shared.b16 {%0,%1,%2,%3}, [%4];"
                 : "=r"(r[0]), "=r"(r[1]), "=r"(r[2]), "=r"(r[3]) : "r"(addr));
}
__device__ __forceinline__ void mma16816(float* c, const uint32_t* a, uint32_t b0, uint32_t b1) {
    asm volatile(
        "mma.sync.aligned.m16n8k16.row.col.f32.bf16.bf16.f32 "
        "{%0,%1,%2,%3}, {%4,%5,%6,%7}, {%8,%9}, {%0,%1,%2,%3};"
        : "+f"(c[0]), "+f"(c[1]), "+f"(c[2]), "+f"(c[3])
        : "r"(a[0]), "r"(a[1]), "r"(a[2]), "r"(a[3]), "r"(b0), "r"(b1));
}
__device__ __forceinline__ void sts16(uint32_t addr, uint4 v) {
    asm volatile("st.shared.v4.b32 [%0], {%1, %2, %3, %4};"
                 :: "r"(addr), "r"(v.x), "r"(v.y), "r"(v.z), "r"(v.w));
}

// ---------- codebook conversion: 16 threads/codeword, 128 blocks ----------
__global__ void __launch_bounds__(128) vq_convE(const float* __restrict__ emb,
                                                float* __restrict__ out, int out_size) {
    int t = blockIdx.x * 128 + threadIdx.x;     // 0 .. 16K-1
    if (t == 0) {
        g_flag_count = 0;
        if (out_size > QELEMS) out[QELEMS] = 0.f;   // zero loss accumulator
    }
    int k = t >> 4, j = t & 15;                 // j: which 4-dim slice
    float4 f4 = *reinterpret_cast<const float4*>(emb + (size_t)k * D + j * 4);
    float f[4] = {f4.x, f4.y, f4.z, f4.w};
    __nv_bfloat16 h[4], m[4];
    float s = 0.f;
#pragma unroll
    for (int e = 0; e < 4; e++) {
        s += f[e] * f[e];
        h[e] = __float2bfloat16_rn(f[e]);
        m[e] = __float2bfloat16_rn(f[e] - __bfloat162float(h[e]));
    }
    uint2 hv = *reinterpret_cast<uint2*>(h);
    uint2 mv = *reinterpret_cast<uint2*>(m);
    uint2* r1 = reinterpret_cast<uint2*>(g_B1 + (size_t)k * 128 + j * 4);
    r1[0] = hv; r1[16] = hv;                    // [h | h] (dup at +64 elems = +16 uint2)
    *reinterpret_cast<uint2*>(g_B2 + (size_t)k * 64 + j * 4) = mv;
    // 16-lane reduction for ||e||^2
#pragma unroll
    for (int off = 8; off > 0; off >>= 1) s += __shfl_xor_sync(0xffffffffu, s, off);
    if (j == 0) g_enorm2[k] = s;
}

// load one B chunk with 128 threads: B1 (64x256B) + B2 (64x128B)
__device__ __forceinline__ void load_B(uint32_t sb, int chunk, int stage, int tid) {
    uint32_t base = sb + OFF_B + stage * 24576;
    const char* s1 = reinterpret_cast<const char*>(g_B1 + (size_t)chunk * NCHUNK * 128);
    const char* s2 = reinterpret_cast<const char*>(g_B2 + (size_t)chunk * NCHUNK * 64);
#pragma unroll
    for (int it = 0; it < 8; it++) {
        int i = tid + it * BLOCK;               // 0..1023
        int row = i >> 4, seg = i & 15;
        cp16(base + row * 256 + ((seg ^ (row & 7)) << 4), s1 + row * 256 + seg * 16);
    }
#pragma unroll
    for (int it = 0; it < 4; it++) {
        int i = tid + it * BLOCK;               // 0..511
        int row = i >> 3, seg = i & 7;
        cp16(base + 16384 + row * 128 + ((seg ^ (row & 7)) << 4), s2 + row * 128 + seg * 16);
    }
}

#define UPD(dv, nn, B1v, I1v, B2v) \
    if ((dv) < (B1v)) { (B2v) = (B1v); (B1v) = (dv); (I1v) = (nn); } \
    else if ((dv) < (B2v)) { (B2v) = (dv); }

#define MERGE(B1v, I1v, B2v, off) { \
    float p1 = __shfl_xor_sync(0xffffffffu, B1v, off); \
    int   pi = __shfl_xor_sync(0xffffffffu, I1v, off); \
    float p2 = __shfl_xor_sync(0xffffffffu, B2v, off); \
    if (p1 < (B1v) || (p1 == (B1v) && pi < (I1v))) { (B2v) = fminf((B1v), p2); (B1v) = p1; (I1v) = pi; } \
    else                                            { (B2v) = fminf((B2v), p1); } }

// ---------- mega kernel: A-convert + GEMM (2 A-blocks/warp) + argmin + finalize ----------
__global__ void __launch_bounds__(BLOCK, 2) vq_gemm(const float* __restrict__ x,
                                                    const float* __restrict__ emb,
                                                    float* __restrict__ out, int out_size) {
    extern __shared__ char sm[];
    uint32_t sb = smem_u32(sm);
    const int tid = threadIdx.x, wid = tid >> 5, l = tid & 31;

    // async loads: e-norms + B0 (G0), B1 (G1)
#pragma unroll
    for (int it = 0; it < 2; it++)
        cp16(sb + OFF_SN + (tid + it * BLOCK) * 16,
             reinterpret_cast<const char*>(g_enorm2) + (tid + it * BLOCK) * 16);
    load_B(sb, 0, 0, tid);
    cp_commit();                                // G0
    load_B(sb, 1, 1, tid);
    cp_commit();                                // G1

    // A tile: one row per thread, split h/m, STS swizzled
    {
        const int row = tid;
        const float4* xr = reinterpret_cast<const float4*>(
            x + (size_t)(blockIdx.x * MTILE + row) * D);
        uint32_t abase = sb + OFF_A + row * 256;
#pragma unroll
        for (int i = 0; i < 8; i++) {           // 8 x (8 floats -> 16B h + 16B m)
            float4 a = xr[2 * i], b = xr[2 * i + 1];
            float f[8] = {a.x, a.y, a.z, a.w, b.x, b.y, b.z, b.w};
            __nv_bfloat16 h[8], m[8];
#pragma unroll
            for (int e = 0; e < 8; e++) {
                h[e] = __float2bfloat16_rn(f[e]);
                m[e] = __float2bfloat16_rn(f[e] - __bfloat162float(h[e]));
            }
            sts16(abase + ((i ^ (row & 7)) << 4),       *reinterpret_cast<uint4*>(h));
            sts16(abase + (((8 + i) ^ (row & 7)) << 4), *reinterpret_cast<uint4*>(m));
        }
    }

    cp_wait<1>();
    __syncthreads();

    // hoist A fragments: 2 blocks of 16 rows per warp, 8 k-steps each
    uint32_t aF[2][8][4];
#pragma unroll
    for (int a = 0; a < 2; a++) {
        int row = (wid << 5) + (a << 4) + (l & 15);
        uint32_t rb = sb + OFF_A + row * 256;
#pragma unroll
        for (int j = 0; j < 8; j++) {
            int seg = j * 2 + (l >> 4);
            ldsm4(aF[a][j], rb + ((seg ^ (row & 7)) << 4));
        }
    }
    const float* snp = reinterpret_cast<const float*>(sm + OFF_SN);

    float b1a = 3.4e38f, b2a = 3.4e38f, b1b = 3.4e38f, b2b = 3.4e38f;
    float b1c = 3.4e38f, b2c = 3.4e38f, b1d = 3.4e38f, b2d = 3.4e38f;
    int i1a = 0, i1b = 0, i1c = 0, i1d = 0;

    for (int c = 0; c < NCHUNKS; c++) {
        if (c > 0) { cp_wait<1>(); __syncthreads(); }
        uint32_t stage = sb + OFF_B + (c & 1) * 24576;

        float C[2][8][4];
#pragma unroll
        for (int a = 0; a < 2; a++)
#pragma unroll
            for (int t = 0; t < 8; t++) { C[a][t][0]=C[a][t][1]=C[a][t][2]=C[a][t][3]=0.f; }

        // [h|m] x [h|h] (8 k-steps): 1 B-ldsm feeds 4 HMMA
#pragma unroll
        for (int j = 0; j < 8; j++) {
#pragma unroll
            for (int g = 0; g < 4; g++) {
                int row = (g << 4) + (l & 15);
                int seg = j * 2 + (l >> 4);
                uint32_t r[4];
                ldsm4(r, stage + row * 256 + ((seg ^ (row & 7)) << 4));
                mma16816(C[0][2*g],   aF[0][j], r[0], r[2]);
                mma16816(C[0][2*g+1], aF[0][j], r[1], r[3]);
                mma16816(C[1][2*g],   aF[1][j], r[0], r[2]);
                mma16816(C[1][2*g+1], aF[1][j], r[1], r[3]);
            }
        }
        // h x [m] (4 k-steps)
#pragma unroll
        for (int j = 0; j < 4; j++) {
#pragma unroll
            for (int g = 0; g < 4; g++) {
                int row = (g << 4) + (l & 15);
                int seg = j * 2 + (l >> 4);
                uint32_t r[4];
                ldsm4(r, stage + 16384 + row * 128 + ((seg ^ (row & 7)) << 4));
                mma16816(C[0][2*g],   aF[0][j], r[0], r[2]);
                mma16816(C[0][2*g+1], aF[0][j], r[1], r[3]);
                mma16816(C[1][2*g],   aF[1][j], r[0], r[2]);
                mma16816(C[1][2*g+1], aF[1][j], r[1], r[3]);
            }
        }

        // epilogue: two-min tracking for 4 row-slots
#pragma unroll
        for (int t = 0; t < 8; t++) {
            int n0 = c * NCHUNK + t * 8 + 2 * (l & 3);
            float s0 = snp[n0], s1 = snp[n0 + 1];
            float d;
            d = fmaf(-2.f, C[0][t][0], s0); UPD(d, n0,     b1a, i1a, b2a);
            d = fmaf(-2.f, C[0][t][1], s1); UPD(d, n0 + 1, b1a, i1a, b2a);
            d = fmaf(-2.f, C[0][t][2], s0); UPD(d, n0,     b1b, i1b, b2b);
            d = fmaf(-2.f, C[0][t][3], s1); UPD(d, n0 + 1, b1b, i1b, b2b);
            d = fmaf(-2.f, C[1][t][0], s0); UPD(d, n0,     b1c, i1c, b2c);
            d = fmaf(-2.f, C[1][t][1], s1); UPD(d, n0 + 1, b1c, i1c, b2c);
            d = fmaf(-2.f, C[1][t][2], s0); UPD(d, n0,     b1d, i1d, b2d);
            d = fmaf(-2.f, C[1][t][3], s1); UPD(d, n0 + 1, b1d, i1d, b2d);
        }

        __syncthreads();
        if (c + 2 < NCHUNKS) load_B(sb, c + 2, c & 1, tid);
        cp_commit();
    }

    // cross-lane merge within 4-lane groups
#pragma unroll
    for (int off = 1; off <= 2; off <<= 1) {
        MERGE(b1a, i1a, b2a, off);
        MERGE(b1b, i1b, b2b, off);
        MERGE(b1c, i1c, b2c, off);
        MERGE(b1d, i1d, b2d, off);
    }

    int* sidx = reinterpret_cast<int*>(sm + OFF_IDX);
    int* sflg = reinterpret_cast<int*>(sm + OFF_FLG);
    if ((l & 3) == 0) {
        int r0 = (wid << 5) + (l >> 2);         // rows r0, +8, +16, +24
        int v = blockIdx.x * MTILE + r0;
        int fa = (b2a - b1a <= EPS), fb = (b2b - b1b <= EPS);
        int fc = (b2c - b1c <= EPS), fd = (b2d - b1d <= EPS);
        sidx[r0]      = i1a; sflg[r0]      = fa;
        sidx[r0 + 8]  = i1b; sflg[r0 + 8]  = fb;
        sidx[r0 + 16] = i1c; sflg[r0 + 16] = fc;
        sidx[r0 + 24] = i1d; sflg[r0 + 24] = fd;
        if (fa) { int s = atomicAdd(&g_flag_count, 1); g_flag_list[s] = v; }
        if (fb) { int s = atomicAdd(&g_flag_count, 1); g_flag_list[s] = v + 8; }
        if (fc) { int s = atomicAdd(&g_flag_count, 1); g_flag_list[s] = v + 16; }
        if (fd) { int s = atomicAdd(&g_flag_count, 1); g_flag_list[s] = v + 24; }
    }
    __syncthreads();

    // fused finalize for non-flagged vectors (1 thread/vector)
    {
        const int r = tid;
        const int v = blockIdx.x * MTILE + r;
        float lsum = 0.f;
        if (!sflg[r]) {
            int bi = sidx[r];
            const float4* er = reinterpret_cast<const float4*>(emb + (size_t)bi * D);
            const float4* xr = reinterpret_cast<const float4*>(x + (size_t)v * D);
            float4* o = reinterpret_cast<float4*>(out + (size_t)v * D);
#pragma unroll
            for (int i = 0; i < 16; i++) {
                float4 e = er[i]; float4 xx = xr[i];
                float dx = e.x - xx.x, dy = e.y - xx.y, dz = e.z - xx.z, dw = e.w - xx.w;
                lsum += dx * dx + dy * dy + dz * dz + dw * dw;
                float4 q;   // quantized = x + (e - x)
                q.x = xx.x + dx; q.y = xx.y + dy; q.z = xx.z + dz; q.w = xx.w + dw;
                o[i] = q;
            }
            if (QELEMS + 1 + v < out_size) out[QELEMS + 1 + v] = (float)bi;
        }
#pragma unroll
        for (int off = 16; off > 0; off >>= 1)
            lsum += __shfl_down_sync(0xffffffffu, lsum, off);
        float* sred = reinterpret_cast<float*>(sm + OFF_RED);
        if (l == 0) sred[wid] = lsum;
        __syncthreads();
        if (wid == 0) {
            float s = (l < 4) ? sred[l] : 0.f;
#pragma unroll
            for (int off = 2; off > 0; off >>= 1)
                s += __shfl_down_sync(0xffffffffu, s, off);
            if (l == 0 && out_size > QELEMS)
                atomicAdd(out + QELEMS, s * (0.25f / (float)QELEMS));
        }
    }
}

// ---------- exact rescan + full finalize for flagged vectors ----------
__global__ void __launch_bounds__(256) vq_rescan(const float* __restrict__ x,
                                                 const float* __restrict__ emb,
                                                 float* __restrict__ out, int out_size) {
    __shared__ float sx[64];
    __shared__ float sbest[256];
    __shared__ int   sidx[256];
    int n = g_flag_count;
    if (n > NVEC) n = NVEC;
    for (int vi = blockIdx.x; vi < n; vi += gridDim.x) {
        int v = g_flag_list[vi];
        __syncthreads();
        if (threadIdx.x < 16)
            reinterpret_cast<float4*>(sx)[threadIdx.x] =
                reinterpret_cast<const float4*>(x + (size_t)v * D)[threadIdx.x];
        __syncthreads();
        float best = 3.4e38f; int bi = K;
#pragma unroll
        for (int kk = 0; kk < 4; kk++) {
            int k = kk * 256 + threadIdx.x;
            const float4* er = reinterpret_cast<const float4*>(emb + (size_t)k * D);
            float dot = 0.f;
#pragma unroll
            for (int i = 0; i < 16; i++) {
                float4 e = er[i];
                dot += sx[4*i] * e.x + sx[4*i+1] * e.y + sx[4*i+2] * e.z + sx[4*i+3] * e.w;
            }
            float d = fmaf(-2.f, dot, g_enorm2[k]);
            if (d < best) { best = d; bi = k; }
        }
        sbest[threadIdx.x] = best; sidx[threadIdx.x] = bi;
        __syncthreads();
        for (int s = 128; s > 0; s >>= 1) {
            if (threadIdx.x < s) {
                float ob = sbest[threadIdx.x + s]; int oi = sidx[threadIdx.x + s];
                if (ob < sbest[threadIdx.x] ||
                    (ob == sbest[threadIdx.x] && oi < sidx[threadIdx.x])) {
                    sbest[threadIdx.x] = ob; sidx[threadIdx.x] = oi;
                }
            }
            __syncthreads();
        }
        int bfin = sidx[0];
        float lsum = 0.f;
        if (threadIdx.x < 16) {
            float4 e  = reinterpret_cast<const float4*>(emb + (size_t)bfin * D)[threadIdx.x];
            float4 xx = reinterpret_cast<const float4*>(x + (size_t)v * D)[threadIdx.x];
            float dx = e.x - xx.x, dy = e.y - xx.y, dz = e.z - xx.z, dw = e.w - xx.w;
            lsum = dx * dx + dy * dy + dz * dz + dw * dw;
            float4 q;
            q.x = xx.x + dx; q.y = xx.y + dy; q.z = xx.z + dz; q.w = xx.w + dw;
            reinterpret_cast<float4*>(out + (size_t)v * D)[threadIdx.x] = q;
        }
        if (threadIdx.x < 32) {
#pragma unroll
            for (int off = 8; off > 0; off >>= 1)
                lsum += __shfl_down_sync(0xffffffffu, lsum, off);
            if (threadIdx.x == 0) {
                if (out_size > QELEMS)
                    atomicAdd(out + QELEMS, lsum * (0.25f / (float)QELEMS));
                if (QELEMS + 1 + v < out_size) out[QELEMS + 1 + v] = (float)bfin;
            }
        }
    }
}

extern "C" void kernel_launch(void* const* d_in, const int* in_sizes, int n_in,
                              void* d_out, int out_size) {
    const float* x   = (const float*)d_in[0];
    const float* emb = (const float*)d_in[1];
    if (n_in >= 2 && in_sizes[0] == K * D && in_sizes[1] == QELEMS) {
        const float* t = x; x = emb; emb = t;
    }
    float* out = (float*)d_out;

    cudaFuncSetAttribute(vq_gemm, cudaFuncAttributeMaxDynamicSharedMemorySize, SMEM_SZ);

    vq_convE<<<K * 16 / 128, 128>>>(emb, out, out_size);   // also zeroes loss slot
    vq_gemm<<<GRID, BLOCK, SMEM_SZ>>>(x, emb, out, out_size);
    vq_rescan<<<256, 256>>>(x, emb, out, out_size);
}